// round 17
// baseline (speedup 1.0000x reference)
#include <cuda_runtime.h>
#include <cuda_fp16.h>
#include <cstdint>

#define NN 50000
#define EE 800000
#define CC 512     // H*HID
#define HH 8
#define FF 64

// ---------------- scratch (device globals; no allocation allowed) ----------
__device__ __align__(16) __half g_feat[(size_t)NN * CC];  // 51.2 MB fp16 features
__device__ float g_el[NN * HH];
__device__ float g_er[NN * HH];
__device__ __align__(16) __half g_h[NN * FF];             // activations (fp16)
__device__ __align__(16) __half g_xh[(size_t)NN * 128];   // x converted
__device__ __align__(16) __half g_w1h[CC * 128];
__device__ __align__(16) __half g_w2h[CC * FF];
__device__ __align__(16) __half g_w3h[CC * FF];
__device__ __align__(16) __half g_wmh[FF * FF];
__device__ int   g_rowptr[NN + 1];
__device__ int   g_cnt[NN];
__device__ int   g_fill[NN];
__device__ int   g_col[EE];

// ---------------- fp32 -> fp16 convert -------------------------------------
__global__ void k_cvt(const float* __restrict__ in, __half* __restrict__ out, int n4) {
    int i = blockIdx.x * blockDim.x + threadIdx.x;
    if (i < n4) {
        float4 v = ((const float4*)in)[i];
        __half2 h0 = __floats2half2_rn(v.x, v.y);
        __half2 h1 = __floats2half2_rn(v.z, v.w);
        uint2 u;
        u.x = *(uint32_t*)&h0;
        u.y = *(uint32_t*)&h1;
        ((uint2*)out)[i] = u;
    }
}

// ---------------- CSR build ------------------------------------------------
__global__ void k_hist(const int* __restrict__ dst) {
    int e = blockIdx.x * blockDim.x + threadIdx.x;
    if (e < EE) atomicAdd(&g_cnt[dst[e]], 1);
}

__global__ void k_scan() {
    __shared__ int sh[1024];
    __shared__ int s_off;
    int tid = threadIdx.x;
    if (tid == 0) s_off = 0;
    __syncthreads();
    for (int base = 0; base < NN; base += 1024) {
        int idx = base + tid;
        int orig = (idx < NN) ? g_cnt[idx] : 0;
        int v = orig;
        sh[tid] = v;
        __syncthreads();
        for (int off = 1; off < 1024; off <<= 1) {
            int add = (tid >= off) ? sh[tid - off] : 0;
            __syncthreads();
            v += add; sh[tid] = v;
            __syncthreads();
        }
        int myoff = s_off;
        if (idx < NN) g_rowptr[idx] = myoff + (v - orig);
        __syncthreads();
        if (tid == 1023) s_off = myoff + v;
        __syncthreads();
    }
    if (tid == 0) g_rowptr[NN] = s_off;
}

__global__ void k_scatter(const int* __restrict__ src, const int* __restrict__ dst) {
    int e = blockIdx.x * blockDim.x + threadIdx.x;
    if (e < EE) {
        int d = dst[e];
        int pos = g_rowptr[d] + atomicAdd(&g_fill[d], 1);
        g_col[pos] = src[e];
    }
}

// ---------------- fp16 GEMM via ldmatrix + mma m16n8k16 --------------------
__device__ __forceinline__ void store_c(float* C, size_t idx, float v) { C[idx] = v; }
__device__ __forceinline__ void store_c(__half* C, size_t idx, float v) { C[idx] = __float2half_rn(v); }

#define LDSM4(r0, r1, r2, r3, addr) \
    asm volatile("ldmatrix.sync.aligned.m8n8.x4.shared.b16 {%0,%1,%2,%3}, [%4];" \
                 : "=r"(r0), "=r"(r1), "=r"(r2), "=r"(r3) : "r"(addr))

template <typename OutT>
__global__ __launch_bounds__(256, 2) void k_gemm_tc(
    const __half* __restrict__ A, const __half* __restrict__ B,
    const float* __restrict__ bias, OutT* __restrict__ C,
    const float* __restrict__ al, const float* __restrict__ ar,
    int M, int NCol, int K)
{
    __shared__ __align__(16) uint8_t smem[32768];
    const int tid = threadIdx.x;
    const int lane = tid & 31, wid = tid >> 5;
    const int wm = wid & 3, wn = wid >> 2;
    const int m0 = blockIdx.y * 128, n0 = blockIdx.x * 128;
    const uint32_t sbase = (uint32_t)__cvta_generic_to_shared(smem);

    float acc[2][8][4];
#pragma unroll
    for (int im = 0; im < 2; im++)
#pragma unroll
        for (int in = 0; in < 8; in++)
#pragma unroll
            for (int q = 0; q < 4; q++) acc[im][in][q] = 0.f;

    int sOff[2];
    size_t gA[2], gB[2];
    bool vA2[2], vB2[2];
#pragma unroll
    for (int i = 0; i < 2; i++) {
        int idx = tid + 256 * i;
        int row = idx >> 2, c0h = (idx & 3) * 8;
        int u = c0h >> 3;
        sOff[i] = row * 64 + ((u ^ ((row >> 1) & 3)) << 4);
        vA2[i] = (m0 + row) < M;
        vB2[i] = (n0 + row) < NCol;
        gA[i] = (size_t)(m0 + row) * K + c0h;
        gB[i] = (size_t)(n0 + row) * K + c0h;
    }

    uint32_t aAddr[2], bAddr[4];
    {
        int rl = (lane & 7) + ((lane >> 3) & 1) * 8;
        int uA = lane >> 4;
#pragma unroll
        for (int im = 0; im < 2; im++) {
            int r = wm * 32 + im * 16 + rl;
            aAddr[im] = r * 64 + ((uA ^ ((r >> 1) & 3)) << 4);
        }
#pragma unroll
        for (int ip = 0; ip < 4; ip++) {
            int r = wn * 64 + ip * 16 + rl;
            bAddr[ip] = 8192 + r * 64 + ((uA ^ ((r >> 1) & 3)) << 4);
        }
    }

    uint4 rA[2], rB[2];
    const uint4 z4 = make_uint4(0, 0, 0, 0);
#pragma unroll
    for (int i = 0; i < 2; i++) {
        rA[i] = vA2[i] ? *(const uint4*)(A + gA[i]) : z4;
        rB[i] = vB2[i] ? *(const uint4*)(B + gB[i]) : z4;
    }
#pragma unroll
    for (int i = 0; i < 2; i++) {
        *(uint4*)(smem + sOff[i]) = rA[i];
        *(uint4*)(smem + 8192 + sOff[i]) = rB[i];
    }
    __syncthreads();

    const int nslab = K >> 5;
    for (int it = 0; it < nslab; it++) {
        if (it + 1 < nslab) {
            int kt = (it + 1) << 5;
#pragma unroll
            for (int i = 0; i < 2; i++) {
                rA[i] = vA2[i] ? *(const uint4*)(A + gA[i] + kt) : z4;
                rB[i] = vB2[i] ? *(const uint4*)(B + gB[i] + kt) : z4;
            }
        }

        const uint32_t bb = sbase + ((it & 1) << 14);
#pragma unroll
        for (int ks = 0; ks < 2; ks++) {
            const uint32_t kx = ks << 5;
            uint32_t a[2][4];
#pragma unroll
            for (int im = 0; im < 2; im++)
                LDSM4(a[im][0], a[im][1], a[im][2], a[im][3], bb + (aAddr[im] ^ kx));
#pragma unroll
            for (int ip = 0; ip < 4; ip++) {
                uint32_t r0, r1, r2, r3;
                LDSM4(r0, r1, r2, r3, bb + (bAddr[ip] ^ kx));
#pragma unroll
                for (int im = 0; im < 2; im++) {
                    asm volatile(
                        "mma.sync.aligned.m16n8k16.row.col.f32.f16.f16.f32 "
                        "{%0,%1,%2,%3},{%4,%5,%6,%7},{%8,%9},{%0,%1,%2,%3};"
                        : "+f"(acc[im][2 * ip][0]), "+f"(acc[im][2 * ip][1]),
                          "+f"(acc[im][2 * ip][2]), "+f"(acc[im][2 * ip][3])
                        : "r"(a[im][0]), "r"(a[im][1]), "r"(a[im][2]), "r"(a[im][3]),
                          "r"(r0), "r"(r2));
                    asm volatile(
                        "mma.sync.aligned.m16n8k16.row.col.f32.f16.f16.f32 "
                        "{%0,%1,%2,%3},{%4,%5,%6,%7},{%8,%9},{%0,%1,%2,%3};"
                        : "+f"(acc[im][2 * ip + 1][0]), "+f"(acc[im][2 * ip + 1][1]),
                          "+f"(acc[im][2 * ip + 1][2]), "+f"(acc[im][2 * ip + 1][3])
                        : "r"(a[im][0]), "r"(a[im][1]), "r"(a[im][2]), "r"(a[im][3]),
                          "r"(r1), "r"(r3));
                }
            }
        }

        if (it + 1 < nslab) {
            uint8_t* wbuf = smem + (((it + 1) & 1) << 14);
#pragma unroll
            for (int i = 0; i < 2; i++) {
                *(uint4*)(wbuf + sOff[i]) = rA[i];
                *(uint4*)(wbuf + 8192 + sOff[i]) = rB[i];
            }
            __syncthreads();
        }
    }

    int gid = lane >> 2, tig = lane & 3;
#pragma unroll
    for (int im = 0; im < 2; im++) {
        int r = m0 + wm * 32 + im * 16 + gid;
#pragma unroll
        for (int in = 0; in < 8; in++) {
            int c = n0 + wn * 64 + in * 8 + tig * 2;
            if (c < NCol) {
                float b0v = bias ? bias[c] : 0.f;
                float b1v = bias ? bias[c + 1] : 0.f;
                if (r < M) {
                    store_c(C, (size_t)r * NCol + c,     acc[im][in][0] + b0v);
                    store_c(C, (size_t)r * NCol + c + 1, acc[im][in][1] + b1v);
                }
                if (r + 8 < M) {
                    store_c(C, (size_t)(r + 8) * NCol + c,     acc[im][in][2] + b0v);
                    store_c(C, (size_t)(r + 8) * NCol + c + 1, acc[im][in][3] + b1v);
                }
            }
        }
    }

    if (al != nullptr) {
        int head = blockIdx.x * 2 + wn;
        const float* alh = al + head * FF;
        const float* arh = ar + head * FF;
        float sl[2][2] = {}, sr[2][2] = {};
#pragma unroll
        for (int im = 0; im < 2; im++)
#pragma unroll
            for (int in = 0; in < 8; in++) {
                int cc0 = in * 8 + tig * 2;
                float a0 = alh[cc0], a1 = alh[cc0 + 1];
                float r0 = arh[cc0], r1 = arh[cc0 + 1];
                sl[im][0] += acc[im][in][0] * a0 + acc[im][in][1] * a1;
                sl[im][1] += acc[im][in][2] * a0 + acc[im][in][3] * a1;
                sr[im][0] += acc[im][in][0] * r0 + acc[im][in][1] * r1;
                sr[im][1] += acc[im][in][2] * r0 + acc[im][in][3] * r1;
            }
#pragma unroll
        for (int o = 1; o <= 2; o <<= 1)
#pragma unroll
            for (int im = 0; im < 2; im++)
#pragma unroll
                for (int hq = 0; hq < 2; hq++) {
                    sl[im][hq] += __shfl_xor_sync(0xffffffffu, sl[im][hq], o);
                    sr[im][hq] += __shfl_xor_sync(0xffffffffu, sr[im][hq], o);
                }
        if (tig == 0) {
#pragma unroll
            for (int im = 0; im < 2; im++) {
                int r = m0 + wm * 32 + im * 16 + gid;
                if (r < M) {
                    g_el[r * HH + head] = sl[im][0];
                    g_er[r * HH + head] = sr[im][0];
                }
                if (r + 8 < M) {
                    g_el[(r + 8) * HH + head] = sl[im][1];
                    g_er[(r + 8) * HH + head] = sr[im][1];
                }
            }
        }
    }
}

// ---------------- aggregate: warp per node, depth-2 pipelined --------------
// Lane layout as before (hA = lane>>3, hB = hA+4, 8 feats each). The edge
// loop keeps 2 edges in flight: iteration i issues edge i+2's col/el/feat
// loads, then consumes edge i's registers (loaded 2 iterations ago).
__global__ __launch_bounds__(256) void k_agg(const float* __restrict__ bias, __half* __restrict__ y) {
    int n = blockIdx.x * 8 + (threadIdx.x >> 5);
    int lane = threadIdx.x & 31;
    int hA = lane >> 3, hB = hA + 4;
    int fj = (lane & 7) * 8;
    int beg = g_rowptr[n], end = g_rowptr[n + 1];
    int deg = end - beg;
    float er_l = (lane < 8) ? __ldg(&g_er[n * HH + lane]) : 0.f;

    float accA[8] = {}, accB[8] = {};
    float ssA = 0.f, ssB = 0.f;
    const uint4 z4 = make_uint4(0, 0, 0, 0);

    float elA = 0.f, elB = 0.f;
    uint4 vA0 = z4, vA1 = z4, vB0 = z4, vB1 = z4;
    if (deg > 0) {
        int s = __ldg(&g_col[beg]);
        elA = (lane < 8) ? __ldg(&g_el[s * HH + lane]) : 0.f;
        const uint4* fr = (const uint4*)(g_feat + (size_t)s * CC) + lane;
        vA0 = __ldcs(fr);
        vA1 = __ldcs(fr + 32);
    }
    if (deg > 1) {
        int s = __ldg(&g_col[beg + 1]);
        elB = (lane < 8) ? __ldg(&g_el[s * HH + lane]) : 0.f;
        const uint4* fr = (const uint4*)(g_feat + (size_t)s * CC) + lane;
        vB0 = __ldcs(fr);
        vB1 = __ldcs(fr + 32);
    }

    for (int i = 0; i < deg; i++) {
        float elC = 0.f;
        uint4 vC0 = z4, vC1 = z4;
        if (i + 2 < deg) {
            int s = __ldg(&g_col[beg + i + 2]);
            elC = (lane < 8) ? __ldg(&g_el[s * HH + lane]) : 0.f;
            const uint4* fr = (const uint4*)(g_feat + (size_t)s * CC) + lane;
            vC0 = __ldcs(fr);
            vC1 = __ldcs(fr + 32);
        }
        float p_mine = 0.f;
        if (lane < 8) {
            float e = elA + er_l;
            e = e > 0.f ? e : 0.2f * e;
            p_mine = __expf(e);
        }
        float pA = __shfl_sync(0xffffffffu, p_mine, hA);
        float pB = __shfl_sync(0xffffffffu, p_mine, hB);
        const __half2* h0 = (const __half2*)&vA0;
        const __half2* h1 = (const __half2*)&vA1;
#pragma unroll
        for (int q = 0; q < 4; q++) {
            float2 fa = __half22float2(h0[q]);
            accA[q * 2]     += pA * fa.x;
            accA[q * 2 + 1] += pA * fa.y;
            float2 fb = __half22float2(h1[q]);
            accB[q * 2]     += pB * fb.x;
            accB[q * 2 + 1] += pB * fb.y;
        }
        ssA += pA; ssB += pB;
        elA = elB; vA0 = vB0; vA1 = vB1;
        elB = elC; vB0 = vC0; vB1 = vC1;
    }
    float invA = (deg > 0) ? 1.f / ssA : 0.f;
    float invB = (deg > 0) ? 1.f / ssB : 0.f;

    float val[8];
#pragma unroll
    for (int k = 0; k < 8; k++)
        val[k] = accA[k] * invA + __ldg(&bias[hA * FF + fj + k])
               + accB[k] * invB + __ldg(&bias[hB * FF + fj + k]);
#pragma unroll
    for (int o = 8; o <= 16; o <<= 1)
#pragma unroll
        for (int k = 0; k < 8; k++) val[k] += __shfl_xor_sync(0xffffffffu, val[k], o);

    if (lane < 8) {
        __half2 o2[4];
#pragma unroll
        for (int q = 0; q < 4; q++) {
            float v0 = val[q * 2],     l0 = v0 > 0.f ? v0 : 0.01f * v0;
            float v1 = val[q * 2 + 1], l1 = v1 > 0.f ? v1 : 0.01f * v1;
            o2[q] = __floats2half2_rn(l0, l1);
        }
        *(uint4*)(y + (size_t)n * FF + lane * 8) = *(uint4*)o2;
    }
}

// ---------------- launcher -------------------------------------------------
extern "C" void kernel_launch(void* const* d_in, const int* in_sizes, int n_in,
                              void* d_out, int out_size) {
    const float* x   = (const float*)d_in[0];
    const int*   src = (const int*)d_in[1];
    const int*   dst = (const int*)d_in[2];
    const float* W1  = (const float*)d_in[3];
    const float* al1 = (const float*)d_in[4];
    const float* ar1 = (const float*)d_in[5];
    const float* b1  = (const float*)d_in[6];
    const float* W2  = (const float*)d_in[7];
    const float* al2 = (const float*)d_in[8];
    const float* ar2 = (const float*)d_in[9];
    const float* b2  = (const float*)d_in[10];
    const float* W3  = (const float*)d_in[11];
    const float* al3 = (const float*)d_in[12];
    const float* ar3 = (const float*)d_in[13];
    const float* b3  = (const float*)d_in[14];
    const float* Wm  = (const float*)d_in[15];
    const float* bm  = (const float*)d_in[16];
    float* out = (float*)d_out;

    static cudaStream_t s2 = nullptr;
    static cudaEvent_t evF = nullptr, evJ = nullptr;
    if (s2 == nullptr) {
        cudaStreamCreateWithFlags(&s2, cudaStreamNonBlocking);
        cudaEventCreateWithFlags(&evF, cudaEventDisableTiming);
        cudaEventCreateWithFlags(&evJ, cudaEventDisableTiming);
    }

    __half *feat_p, *h_p, *xh_p, *w1_p, *w2_p, *w3_p, *wm_p;
    void *cnt_p, *fill_p;
    cudaGetSymbolAddress((void**)&feat_p, g_feat);
    cudaGetSymbolAddress((void**)&h_p, g_h);
    cudaGetSymbolAddress((void**)&xh_p, g_xh);
    cudaGetSymbolAddress((void**)&w1_p, g_w1h);
    cudaGetSymbolAddress((void**)&w2_p, g_w2h);
    cudaGetSymbolAddress((void**)&w3_p, g_w3h);
    cudaGetSymbolAddress((void**)&wm_p, g_wmh);
    cudaGetSymbolAddress(&cnt_p, g_cnt);
    cudaGetSymbolAddress(&fill_p, g_fill);

    // ---- fork: CSR build + later-layer weight converts on s2 ----
    cudaEventRecord(evF, 0);
    cudaStreamWaitEvent(s2, evF, 0);
    cudaMemsetAsync(cnt_p, 0, NN * sizeof(int), s2);
    cudaMemsetAsync(fill_p, 0, NN * sizeof(int), s2);
    k_hist<<<(EE + 255) / 256, 256, 0, s2>>>(dst);
    k_cvt<<<(CC * FF / 4 + 255) / 256, 256, 0, s2>>>(W2, w2_p, CC * FF / 4);
    k_cvt<<<(CC * FF / 4 + 255) / 256, 256, 0, s2>>>(W3, w3_p, CC * FF / 4);
    k_cvt<<<(FF * FF / 4 + 255) / 256, 256, 0, s2>>>(Wm, wm_p, FF * FF / 4);
    k_scan<<<1, 1024, 0, s2>>>();
    k_scatter<<<(EE + 255) / 256, 256, 0, s2>>>(src, dst);
    cudaEventRecord(evJ, s2);

    // ---- main stream: layer-1 projection chain ----
    k_cvt<<<(NN * 128 / 4 + 255) / 256, 256>>>(x, xh_p, NN * 128 / 4);
    k_cvt<<<(CC * 128 / 4 + 255) / 256, 256>>>(W1, w1_p, CC * 128 / 4);

    dim3 gproj(CC / 128, (NN + 127) / 128);
    k_gemm_tc<__half><<<gproj, 256>>>(xh_p, w1_p, nullptr, feat_p, al1, ar1, NN, CC, 128);
    cudaStreamWaitEvent(0, evJ, 0);
    k_agg<<<NN / 8, 256>>>(b1, h_p);

    // layer 2 (K=64)
    k_gemm_tc<__half><<<gproj, 256>>>(h_p, w2_p, nullptr, feat_p, al2, ar2, NN, CC, 64);
    k_agg<<<NN / 8, 256>>>(b2, h_p);

    // layer 3 (K=64)
    k_gemm_tc<__half><<<gproj, 256>>>(h_p, w3_p, nullptr, feat_p, al3, ar3, NN, CC, 64);
    k_agg<<<NN / 8, 256>>>(b3, h_p);

    // final linear: out = h @ Wm^T + bm  [N,OUT] fp32
    k_gemm_tc<float><<<dim3(1, (NN + 127) / 128), 256>>>(h_p, wm_p, bm, out,
                                                         nullptr, nullptr, NN, FF, FF);
}